// round 10
// baseline (speedup 1.0000x reference)
#include <cuda_runtime.h>

// Discriminator neural-SDE scan. B=512, T=4096, D=8, H=16, W=16.
// ONE warp per batch element (512 x 32). R8 skeleton + chain surgery:
//   P1: lane -> hidden row; y read from SMEM as packed pairs (ulonglong2),
//       8x fma.rn.f32x2 dot; lipswish. hc stored duplicated (h,h).
//   P2: 4 g-rows/lane via row-pair-packed fma2 dots (4 accumulators);
//       4 g-tanhs share ONE RCP (clamp +-10); f row K-split + xor;
//       einsum d-quad + xor; ynew loop-carried in registers (pair-redundant),
//       even lane stores s_y for P1. t-term computed fresh each step, early.
// 2 __syncwarp/step. EX2/RCP-based activations (accuracy-safe).

#define T_STEPS 4096
#define FULLMASK 0xffffffffu
typedef unsigned long long ull;

__device__ __forceinline__ ull fma2(ull a, ull b, ull c) {
    ull r; asm("fma.rn.f32x2 %0, %1, %2, %3;" : "=l"(r) : "l"(a), "l"(b), "l"(c)); return r;
}
__device__ __forceinline__ ull add2(ull a, ull b) {
    ull r; asm("add.rn.f32x2 %0, %1, %2;" : "=l"(r) : "l"(a), "l"(b)); return r;
}
__device__ __forceinline__ ull pack2(float x, float y) {
    ull r; asm("mov.b64 %0, {%1,%2};" : "=l"(r) : "f"(x), "f"(y)); return r;
}
__device__ __forceinline__ float2 unpack2(ull v) {
    float2 r; asm("mov.b64 {%0,%1}, %2;" : "=f"(r.x), "=f"(r.y) : "l"(v)); return r;
}
__device__ __forceinline__ float rcp_fast(float x) {
    float r; asm("rcp.approx.f32 %0, %1;" : "=f"(r) : "f"(x)); return r;
}

// tanh(x) = 1 - 2/(exp(2x)+1); EX2-based (for f).
__device__ __forceinline__ float tanh_fast(float x) {
    float e = __expf(2.f * x);
    return 1.f - __fdividef(2.f, e + 1.f);
}
// lipswish(x) = 0.909 * x * sigmoid(x).
__device__ __forceinline__ float lipswish_fast(float x) {
    float ax = 0.909f * x;
    return ax * __fdividef(1.f, 1.f + __expf(-x));
}

// Four tanhs with ONE shared RCP. Clamp to +-10 (tanh(+-10) == +-1.0f in fp32;
// also bounds the product below FLT_MAX: (e^20+1)^4 ~ 5.5e34).
__device__ __forceinline__ void tanh4_fast(float x0, float x1, float x2, float x3,
                                           float& t0, float& t1, float& t2, float& t3) {
    x0 = fminf(fmaxf(x0, -10.f), 10.f);
    x1 = fminf(fmaxf(x1, -10.f), 10.f);
    x2 = fminf(fmaxf(x2, -10.f), 10.f);
    x3 = fminf(fmaxf(x3, -10.f), 10.f);
    float s0 = __expf(2.f * x0) + 1.f;
    float s1 = __expf(2.f * x1) + 1.f;
    float s2 = __expf(2.f * x2) + 1.f;
    float s3 = __expf(2.f * x3) + 1.f;
    float m01 = s0 * s1, m23 = s2 * s3;
    float r = rcp_fast(m01 * m23);
    float u01 = -2.f * (m23 * r);   // == -2/(s0*s1)
    float u23 = -2.f * (m01 * r);   // == -2/(s2*s3)
    t0 = fmaf(s1, u01, 1.f);        // 1 - 2/s0
    t1 = fmaf(s0, u01, 1.f);
    t2 = fmaf(s3, u23, 1.f);
    t3 = fmaf(s2, u23, 1.f);
}

__global__ void __launch_bounds__(32) sde_scan_kernel(
    const float* __restrict__ ts, const float* __restrict__ ys,
    const float* __restrict__ iW1, const float* __restrict__ ib1,
    const float* __restrict__ iW2, const float* __restrict__ ib2,
    const float* __restrict__ vW1, const float* __restrict__ vb1,
    const float* __restrict__ vW2, const float* __restrict__ vb2,
    const float* __restrict__ cW1, const float* __restrict__ cb1,
    const float* __restrict__ cW2, const float* __restrict__ cb2,
    const float* __restrict__ rW, const float* __restrict__ rb,
    float* __restrict__ out)
{
    const int b    = blockIdx.x;
    const int lane = threadIdx.x & 31;

    __shared__ __align__(16) float  s_y[16];      // y(n)
    __shared__ __align__(16) float  s_hv[16];     // v-hidden
    __shared__ __align__(16) float2 s_hc2[16];    // c-hidden, duplicated (h,h)

    const float t0 = ts[0];
    const float* __restrict__ ysb = ys + (size_t)b * (T_STEPS * 8);

    const int hidx  = lane >> 1;      // h for g rows, f row, y slot
    const int khalf = lane & 1;

    // ---- P1 weights: row = lane; [t-coef | 16 y-coefs] packed as 8 pairs ----
    ull w1p[8]; float w1t, b1r;
    {
        const float* W = (lane < 16) ? (vW1 + lane * 17) : (cW1 + (lane - 16) * 17);
        w1t = W[0];
#pragma unroll
        for (int q = 0; q < 8; q++) w1p[q] = pack2(W[1 + 2 * q], W[2 + 2 * q]);
        b1r = (lane < 16) ? vb1[lane] : cb1[lane - 16];
    }

    // ---- g packed weights: rows 4l..4l+3, row-pair packing ----
    ull cwp01[16], cwp23[16];
    float cbr0, cbr1, cbr2, cbr3;
    {
        const int fl = 4 * lane;
        const float* Wa = cW2 + (fl + 0) * 16;
        const float* Wb = cW2 + (fl + 1) * 16;
        const float* Wc = cW2 + (fl + 2) * 16;
        const float* Wd = cW2 + (fl + 3) * 16;
#pragma unroll
        for (int k = 0; k < 16; k++) {
            cwp01[k] = pack2(Wa[k], Wb[k]);
            cwp23[k] = pack2(Wc[k], Wd[k]);
        }
        cbr0 = cb2[fl]; cbr1 = cb2[fl + 1]; cbr2 = cb2[fl + 2]; cbr3 = cb2[fl + 3];
    }

    // ---- f weights: row hidx, K-half khalf ----
    float vfh[8], fbb;
    {
#pragma unroll
        for (int k = 0; k < 8; k++) vfh[k] = vW2[hidx * 16 + khalf * 8 + k];
        fbb = (khalf == 0) ? vb2[hidx] : 0.f;
    }

    // ---- initial MLP: y0 = relu([t0, ys0] @ iW1^T + ib1) @ iW2^T + ib2 ----
    float ynew;   // this lane's y[hidx] (pair-redundant), loop-carried
    {
        float a = 0.f;
        if (lane < 16) {
            a = fmaf(iW1[lane * 9], t0, ib1[lane]);
#pragma unroll
            for (int k = 0; k < 8; k++) a = fmaf(iW1[lane * 9 + 1 + k], ysb[k], a);
            a = fmaxf(a, 0.f);
        }
        float hv[16];
#pragma unroll
        for (int k = 0; k < 16; k++) hv[k] = __shfl_sync(FULLMASK, a, k);
        float y0 = 0.f;
        if (lane < 16) {
            y0 = ib2[lane];
#pragma unroll
            for (int k = 0; k < 16; k++) y0 = fmaf(iW2[lane * 16 + k], hv[k], y0);
            s_y[lane] = y0;
        }
        float yv16[16];
#pragma unroll
        for (int k = 0; k < 16; k++) yv16[k] = __shfl_sync(FULLMASK, y0, k);
        if (lane == 0) {
            float acc = rb[0];
#pragma unroll
            for (int k = 0; k < 16; k++) acc = fmaf(rW[k], yv16[k], acc);
            out[b * 2 + 0] = acc;
        }
        ynew = yv16[0];
        ynew = __shfl_sync(FULLMASK, y0, hidx);
    }
    __syncwarp();

    // ---- dx: lane tracks d-quad d0 = khalf*4 ----
    const int d0 = khalf * 4;
    auto ldrow = [&](int r) -> float4 {
        return *reinterpret_cast<const float4*>(ysb + (size_t)r * 8 + d0);
    };

    float tf = t0;
    float tb = fmaf(w1t, tf, b1r);   // fresh each step; computed off-chain

    // ---- one Euler step ----
    auto step = [&](const float4 pv, const float4 cv) {
        // ===== P1: h(row=lane) = lipswish(W1·[t, y] + b1), packed dot =====
        {
            const ulonglong2* Y2 = reinterpret_cast<const ulonglong2*>(s_y);
            ulonglong2 ya = Y2[0], yb = Y2[1], yc = Y2[2], yd = Y2[3];
            ull p0 = 0, p1 = 0;
            p0 = fma2(w1p[0], ya.x, p0);  p1 = fma2(w1p[1], ya.y, p1);
            p0 = fma2(w1p[2], yb.x, p0);  p1 = fma2(w1p[3], yb.y, p1);
            p0 = fma2(w1p[4], yc.x, p0);  p1 = fma2(w1p[5], yc.y, p1);
            p0 = fma2(w1p[6], yd.x, p0);  p1 = fma2(w1p[7], yd.y, p1);
            float2 u0 = unpack2(p0), u1 = unpack2(p1);
            float pre = ((u0.x + u0.y) + (u1.x + u1.y)) + tb;
            float h = lipswish_fast(pre);
            if (lane < 16) s_hv[lane] = h;
            else           s_hc2[lane - 16] = make_float2(h, h);
        }
        tf += 1.f;
        tb = fmaf(w1t, tf, b1r);     // next step's t-term, fresh (tf exact int)
        __syncwarp();

        // dx diffs (off-chain)
        float dx0 = cv.x - pv.x, dx1 = cv.y - pv.y;
        float dx2 = cv.z - pv.z, dx3 = cv.w - pv.w;

        // ===== P2 =====
        // hc duplicated pairs
        ull hc2[16];
        {
            const ulonglong2* H2 = reinterpret_cast<const ulonglong2*>(s_hc2);
#pragma unroll
            for (int q = 0; q < 8; q++) {
                ulonglong2 u = H2[q];
                hc2[2 * q] = u.x; hc2[2 * q + 1] = u.y;
            }
        }
        // row-pair packed dots, 4 accumulators each (depth 4)
        ull A0 = 0, A1 = 0, A2 = 0, A3 = 0;
        ull B0 = 0, B1 = 0, B2 = 0, B3 = 0;
#pragma unroll
        for (int k = 0; k < 16; k += 4) {
            A0 = fma2(cwp01[k],     hc2[k],     A0);
            A1 = fma2(cwp01[k + 1], hc2[k + 1], A1);
            A2 = fma2(cwp01[k + 2], hc2[k + 2], A2);
            A3 = fma2(cwp01[k + 3], hc2[k + 3], A3);
            B0 = fma2(cwp23[k],     hc2[k],     B0);
            B1 = fma2(cwp23[k + 1], hc2[k + 1], B1);
            B2 = fma2(cwp23[k + 2], hc2[k + 2], B2);
            B3 = fma2(cwp23[k + 3], hc2[k + 3], B3);
        }
        ull As = add2(add2(A0, A1), add2(A2, A3));
        ull Bs = add2(add2(B0, B1), add2(B2, B3));
        float2 ua = unpack2(As), ub = unpack2(Bs);
        float g0, g1, g2, g3;
        tanh4_fast(ua.x + cbr0, ua.y + cbr1, ub.x + cbr2, ub.y + cbr3,
                   g0, g1, g2, g3);

        // f row hidx, K-half khalf
        float fp;
        {
            const float4* Hv = reinterpret_cast<const float4*>(s_hv);
            float4 va = Hv[khalf * 2 + 0], vb = Hv[khalf * 2 + 1];
            float f0 = fbb, f1 = 0.f, f2 = 0.f, f3 = 0.f;
            f0 = fmaf(vfh[0], va.x, f0); f1 = fmaf(vfh[1], va.y, f1);
            f2 = fmaf(vfh[2], va.z, f2); f3 = fmaf(vfh[3], va.w, f3);
            f0 = fmaf(vfh[4], vb.x, f0); f1 = fmaf(vfh[5], vb.y, f1);
            f2 = fmaf(vfh[6], vb.z, f2); f3 = fmaf(vfh[7], vb.w, f3);
            fp = (f0 + f1) + (f2 + f3);
        }
        fp += __shfl_xor_sync(FULLMASK, fp, 1);
        float fv = tanh_fast(fp);

        // einsum: this lane's d-quad of h = hidx
        float part = g0 * dx0;
        part = fmaf(g1, dx1, part);
        part = fmaf(g2, dx2, part);
        part = fmaf(g3, dx3, part);
        part += __shfl_xor_sync(FULLMASK, part, 1);

        ynew = ynew + fv + part;     // pair-redundant, loop-carried
        if (khalf == 0) s_y[hidx] = ynew;
        __syncwarp();
    };

    // ---- main loop: 4-step bodies with register-rotated row prefetch ----
    float4 rA = ldrow(0), rB = ldrow(1), rC = ldrow(2), rD = ldrow(3);
    int n = 0;
#pragma unroll 1
    for (int it = 0; it < 1023; it++) {   // n = 0..4091, prefetch rows n+4..n+7 <= 4095
        float4 q0 = ldrow(n + 4);
        step(rA, rB);
        float4 q1 = ldrow(n + 5);
        step(rB, rC);
        float4 q2 = ldrow(n + 6);
        step(rC, rD);
        float4 q3 = ldrow(n + 7);
        step(rD, q0);
        rA = q0; rB = q1; rC = q2; rD = q3;
        n += 4;
    }
    // tail: n = 4092, 4093, 4094 (rows already resident)
    step(rA, rB);
    step(rB, rC);
    step(rC, rD);

    // ---- readout of yT ----
    if (lane == 0) {
        float acc = rb[0];
#pragma unroll
        for (int k = 0; k < 16; k++) acc = fmaf(rW[k], s_y[k], acc);
        out[b * 2 + 1] = acc;
    }
}

extern "C" void kernel_launch(void* const* d_in, const int* in_sizes, int n_in,
                              void* d_out, int out_size) {
    const float* ts  = (const float*)d_in[0];
    const float* ys  = (const float*)d_in[1];
    const float* iW1 = (const float*)d_in[2];
    const float* ib1 = (const float*)d_in[3];
    const float* iW2 = (const float*)d_in[4];
    const float* ib2 = (const float*)d_in[5];
    const float* vW1 = (const float*)d_in[6];
    const float* vb1 = (const float*)d_in[7];
    const float* vW2 = (const float*)d_in[8];
    const float* vb2 = (const float*)d_in[9];
    const float* cW1 = (const float*)d_in[10];
    const float* cb1 = (const float*)d_in[11];
    const float* cW2 = (const float*)d_in[12];
    const float* cb2 = (const float*)d_in[13];
    const float* rW  = (const float*)d_in[14];
    const float* rb  = (const float*)d_in[15];

    const int Bn = out_size / 2;  // (B, 2, 1) float32
    sde_scan_kernel<<<Bn, 32>>>(ts, ys, iW1, ib1, iW2, ib2,
                                vW1, vb1, vW2, vb2,
                                cW1, cb1, cW2, cb2, rW, rb,
                                (float*)d_out);
}

// round 11
// speedup vs baseline: 1.1178x; 1.1178x over previous
#include <cuda_runtime.h>

// Discriminator neural-SDE scan. B=512, T=4096, D=8, H=16, W=16.
// R8 math exactly; launch rebalanced: 128-thread blocks, each of the 4 warps
// independently scans ONE batch element (b = blockIdx*4 + wid). No
// __syncthreads anywhere; per-warp SMEM regions; 2 __syncwarp/step.
// Rationale: SMSP = wid%4 -> 32-thread blocks stack all warps on SMSP0;
// 4-warp blocks spread across all 4 SMSPs (issue-bound -> chain-bound).
//   P1: lane -> hidden row (0-15 vW1, 16-31 cW1), full 17-dot on y from SMEM.
//   P2: lane -> g rows 4l..4l+3 (two fma.rn.f32x2 packed dots), f row l>>1
//       (K-split + shfl_xor), einsum d-quad + shfl_xor, lane-local y update.
// EX2/RCP-based activations (accuracy-safe).

#define T_STEPS 4096
#define FULLMASK 0xffffffffu
typedef unsigned long long ull;

__device__ __forceinline__ ull fma2(ull a, ull b, ull c) {
    ull r; asm("fma.rn.f32x2 %0, %1, %2, %3;" : "=l"(r) : "l"(a), "l"(b), "l"(c)); return r;
}
__device__ __forceinline__ ull pack2(float x, float y) {
    ull r; asm("mov.b64 %0, {%1,%2};" : "=l"(r) : "f"(x), "f"(y)); return r;
}
__device__ __forceinline__ float2 unpack2(ull v) {
    float2 r; asm("mov.b64 {%0,%1}, %2;" : "=f"(r.x), "=f"(r.y) : "l"(v)); return r;
}

// tanh(x) = 1 - 2/(exp(2x)+1); EX2-based, branchless, saturates via inf/0.
__device__ __forceinline__ float tanh_fast(float x) {
    float e = __expf(2.f * x);
    return 1.f - __fdividef(2.f, e + 1.f);
}
// lipswish(x) = 0.909 * x * sigmoid(x), EX2-based.
__device__ __forceinline__ float lipswish_fast(float x) {
    float ax = 0.909f * x;
    return ax * __fdividef(1.f, 1.f + __expf(-x));
}

__global__ void __launch_bounds__(128) sde_scan_kernel(
    const float* __restrict__ ts, const float* __restrict__ ys,
    const float* __restrict__ iW1, const float* __restrict__ ib1,
    const float* __restrict__ iW2, const float* __restrict__ ib2,
    const float* __restrict__ vW1, const float* __restrict__ vb1,
    const float* __restrict__ vW2, const float* __restrict__ vb2,
    const float* __restrict__ cW1, const float* __restrict__ cb1,
    const float* __restrict__ cW2, const float* __restrict__ cb2,
    const float* __restrict__ rW, const float* __restrict__ rb,
    float* __restrict__ out)
{
    const int tid  = threadIdx.x;
    const int wid  = tid >> 5;                 // 0..3 -> SMSP 0..3
    const int lane = tid & 31;
    const int b    = blockIdx.x * 4 + wid;     // batch element for this warp

    // per-warp SMEM regions (no inter-warp sharing)
    __shared__ __align__(16) float  s_y[4][16];
    __shared__ __align__(16) float  s_hv[4][16];
    __shared__ __align__(16) float2 s_hc2[4][16];
    float*  sy  = s_y[wid];
    float*  shv = s_hv[wid];
    float2* shc = s_hc2[wid];

    const float t0 = ts[0];
    const float* __restrict__ ysb = ys + (size_t)b * (T_STEPS * 8);

    const int hidx  = lane >> 1;      // h for g rows, f row, y slot
    const int khalf = lane & 1;

    // ---- P1 weights: row = lane; [t-coef | 16 y-coefs] ----
    float w1[16], w1t, b1r;
    {
        const float* W = (lane < 16) ? (vW1 + lane * 17) : (cW1 + (lane - 16) * 17);
        w1t = W[0];
#pragma unroll
        for (int k = 0; k < 16; k++) w1[k] = W[1 + k];
        b1r = (lane < 16) ? vb1[lane] : cb1[lane - 16];
    }

    // ---- g packed weights: rows 4l..4l+3 ----
    ull cwp01[16], cwp23[16];
    float cbr0, cbr1, cbr2, cbr3;
    {
        const int fl = 4 * lane;
        const float* Wa = cW2 + (fl + 0) * 16;
        const float* Wb = cW2 + (fl + 1) * 16;
        const float* Wc = cW2 + (fl + 2) * 16;
        const float* Wd = cW2 + (fl + 3) * 16;
#pragma unroll
        for (int k = 0; k < 16; k++) {
            cwp01[k] = pack2(Wa[k], Wb[k]);
            cwp23[k] = pack2(Wc[k], Wd[k]);
        }
        cbr0 = cb2[fl]; cbr1 = cb2[fl + 1]; cbr2 = cb2[fl + 2]; cbr3 = cb2[fl + 3];
    }

    // ---- f weights: row hidx, K-half khalf ----
    float vfh[8], fbb;
    {
#pragma unroll
        for (int k = 0; k < 8; k++) vfh[k] = vW2[hidx * 16 + khalf * 8 + k];
        fbb = (khalf == 0) ? vb2[hidx] : 0.f;
    }

    // ---- initial MLP: y0 = relu([t0, ys0] @ iW1^T + ib1) @ iW2^T + ib2 ----
    {
        float a = 0.f;
        if (lane < 16) {
            a = fmaf(iW1[lane * 9], t0, ib1[lane]);
#pragma unroll
            for (int k = 0; k < 8; k++) a = fmaf(iW1[lane * 9 + 1 + k], ysb[k], a);
            a = fmaxf(a, 0.f);
        }
        float hv[16];
#pragma unroll
        for (int k = 0; k < 16; k++) hv[k] = __shfl_sync(FULLMASK, a, k);
        float y0 = 0.f;
        if (lane < 16) {
            y0 = ib2[lane];
#pragma unroll
            for (int k = 0; k < 16; k++) y0 = fmaf(iW2[lane * 16 + k], hv[k], y0);
            sy[lane] = y0;
        }
        float yv16[16];
#pragma unroll
        for (int k = 0; k < 16; k++) yv16[k] = __shfl_sync(FULLMASK, y0, k);
        if (lane == 0) {
            float acc = rb[0];
#pragma unroll
            for (int k = 0; k < 16; k++) acc = fmaf(rW[k], yv16[k], acc);
            out[b * 2 + 0] = acc;
        }
    }
    __syncwarp();

    // ---- dx: lane tracks d-quad d0 = khalf*4 ----
    const int d0 = khalf * 4;
    auto ldrow = [&](int r) -> float4 {
        return *reinterpret_cast<const float4*>(ysb + (size_t)r * 8 + d0);
    };

    float tf = t0;

    // ---- one Euler step ----
    auto step = [&](const float4 pv, const float4 cv) {
        // ===== P1: h(row=lane) = lipswish(W1·[t, y] + b1) =====
        {
            const float4* Y4 = reinterpret_cast<const float4*>(sy);
            float4 q0 = Y4[0], q1 = Y4[1], q2 = Y4[2], q3 = Y4[3];
            float a0 = fmaf(w1t, tf, b1r), a1 = 0.f, a2 = 0.f, a3 = 0.f;
            a0 = fmaf(w1[0],  q0.x, a0); a1 = fmaf(w1[1],  q0.y, a1);
            a2 = fmaf(w1[2],  q0.z, a2); a3 = fmaf(w1[3],  q0.w, a3);
            a0 = fmaf(w1[4],  q1.x, a0); a1 = fmaf(w1[5],  q1.y, a1);
            a2 = fmaf(w1[6],  q1.z, a2); a3 = fmaf(w1[7],  q1.w, a3);
            a0 = fmaf(w1[8],  q2.x, a0); a1 = fmaf(w1[9],  q2.y, a1);
            a2 = fmaf(w1[10], q2.z, a2); a3 = fmaf(w1[11], q2.w, a3);
            a0 = fmaf(w1[12], q3.x, a0); a1 = fmaf(w1[13], q3.y, a1);
            a2 = fmaf(w1[14], q3.z, a2); a3 = fmaf(w1[15], q3.w, a3);
            float h = lipswish_fast((a0 + a1) + (a2 + a3));
            if (lane < 16) shv[lane] = h;
            else           shc[lane - 16] = make_float2(h, h);
        }
        tf += 1.f;
        __syncwarp();

        // ===== P2 =====
        float ylane = sy[hidx];   // early scalar load (y(n)[h])

        // hc duplicated pairs
        ull hc2[16];
        {
            const ulonglong2* H2 = reinterpret_cast<const ulonglong2*>(shc);
#pragma unroll
            for (int q = 0; q < 8; q++) {
                ulonglong2 u = H2[q];
                hc2[2 * q] = u.x; hc2[2 * q + 1] = u.y;
            }
        }
        // two packed dots: rows (4l,4l+1) and (4l+2,4l+3)
        ull A0 = 0, A1 = 0, B0 = 0, B1 = 0;
#pragma unroll
        for (int k = 0; k < 16; k += 2) {
            A0 = fma2(cwp01[k],     hc2[k],     A0);
            A1 = fma2(cwp01[k + 1], hc2[k + 1], A1);
            B0 = fma2(cwp23[k],     hc2[k],     B0);
            B1 = fma2(cwp23[k + 1], hc2[k + 1], B1);
        }
        float2 ua0 = unpack2(A0), ua1 = unpack2(A1);
        float2 ub0 = unpack2(B0), ub1 = unpack2(B1);
        float g0 = tanh_fast((ua0.x + ua1.x) + cbr0);
        float g1 = tanh_fast((ua0.y + ua1.y) + cbr1);
        float g2 = tanh_fast((ub0.x + ub1.x) + cbr2);
        float g3 = tanh_fast((ub0.y + ub1.y) + cbr3);

        // f row hidx, K-half khalf
        float fp;
        {
            const float4* Hv = reinterpret_cast<const float4*>(shv);
            float4 va = Hv[khalf * 2 + 0], vb = Hv[khalf * 2 + 1];
            float f0 = fbb, f1 = 0.f, f2 = 0.f, f3 = 0.f;
            f0 = fmaf(vfh[0], va.x, f0); f1 = fmaf(vfh[1], va.y, f1);
            f2 = fmaf(vfh[2], va.z, f2); f3 = fmaf(vfh[3], va.w, f3);
            f0 = fmaf(vfh[4], vb.x, f0); f1 = fmaf(vfh[5], vb.y, f1);
            f2 = fmaf(vfh[6], vb.z, f2); f3 = fmaf(vfh[7], vb.w, f3);
            fp = (f0 + f1) + (f2 + f3);
        }
        fp += __shfl_xor_sync(FULLMASK, fp, 1);
        float fv = tanh_fast(fp);

        // einsum: this lane's d-quad of h = hidx
        float part = g0 * (cv.x - pv.x);
        part = fmaf(g1, cv.y - pv.y, part);
        part = fmaf(g2, cv.z - pv.z, part);
        part = fmaf(g3, cv.w - pv.w, part);
        part += __shfl_xor_sync(FULLMASK, part, 1);

        float ynew = ylane + fv + part;
        if (khalf == 0) sy[hidx] = ynew;
        __syncwarp();
    };

    // ---- main loop: 4-step bodies with register-rotated row prefetch ----
    float4 rA = ldrow(0), rB = ldrow(1), rC = ldrow(2), rD = ldrow(3);
    int n = 0;
#pragma unroll 1
    for (int it = 0; it < 1023; it++) {   // n = 0..4091, prefetch rows n+4..n+7 <= 4095
        float4 q0 = ldrow(n + 4);
        step(rA, rB);
        float4 q1 = ldrow(n + 5);
        step(rB, rC);
        float4 q2 = ldrow(n + 6);
        step(rC, rD);
        float4 q3 = ldrow(n + 7);
        step(rD, q0);
        rA = q0; rB = q1; rC = q2; rD = q3;
        n += 4;
    }
    // tail: n = 4092, 4093, 4094 (rows already resident)
    step(rA, rB);
    step(rB, rC);
    step(rC, rD);

    // ---- readout of yT ----
    if (lane == 0) {
        float acc = rb[0];
#pragma unroll
        for (int k = 0; k < 16; k++) acc = fmaf(rW[k], sy[k], acc);
        out[b * 2 + 1] = acc;
    }
}

extern "C" void kernel_launch(void* const* d_in, const int* in_sizes, int n_in,
                              void* d_out, int out_size) {
    const float* ts  = (const float*)d_in[0];
    const float* ys  = (const float*)d_in[1];
    const float* iW1 = (const float*)d_in[2];
    const float* ib1 = (const float*)d_in[3];
    const float* iW2 = (const float*)d_in[4];
    const float* ib2 = (const float*)d_in[5];
    const float* vW1 = (const float*)d_in[6];
    const float* vb1 = (const float*)d_in[7];
    const float* vW2 = (const float*)d_in[8];
    const float* vb2 = (const float*)d_in[9];
    const float* cW1 = (const float*)d_in[10];
    const float* cb1 = (const float*)d_in[11];
    const float* cW2 = (const float*)d_in[12];
    const float* cb2 = (const float*)d_in[13];
    const float* rW  = (const float*)d_in[14];
    const float* rb  = (const float*)d_in[15];

    const int Bn = out_size / 2;  // (B, 2, 1) float32
    sde_scan_kernel<<<Bn / 4, 128>>>(ts, ys, iW1, ib1, iW2, ib2,
                                     vW1, vb1, vW2, vb2,
                                     cW1, cb1, cW2, cb2, rW, rb,
                                     (float*)d_out);
}